// round 3
// baseline (speedup 1.0000x reference)
#include <cuda_runtime.h>

// SCCT_NGT: 5000-step explicit PDE loop on NX=64 with tiny MLP closure,
// then phi2 = mean(u^2) and histogram entropy H of |u|/max.
//
// One persistent CTA (128 threads = 4 warps, 1 per SMSP), u double-buffered in
// shared memory, one __syncthreads per step. Thread t handles point p = t>>1;
// half = t&1 selects (w1,b1,wc[:16]) vs (w2,b2,wc[16:]); the two halves'
// partial combine sums merge via __shfl_xor(s,1) — no extra barrier.
// tanh(z) = 1 - 2/(exp(2z)+1) with weights pre-scaled by 2*log2(e):
// per hidden unit = 3 FMA (z) + EX2 + FADD + RCP + 1 FMA (folded combine).
// MUFU floor: 32 warp-MUFU/step/warp @ rt 8 = 256 cyc/step — the binding pipe.

#define NXc 64
#define HIDc 16

__device__ __forceinline__ float ex2f(float x) {
    float y; asm("ex2.approx.f32 %0, %1;" : "=f"(y) : "f"(x)); return y;
}
__device__ __forceinline__ float rcpf(float x) {
    float y; asm("rcp.approx.f32 %0, %1;" : "=f"(y) : "f"(x)); return y;
}

__global__ __launch_bounds__(128, 1)
void scct_kernel(const float* __restrict__ u0,
                 const float* __restrict__ w1, const float* __restrict__ b1,
                 const float* __restrict__ w2, const float* __restrict__ b2,
                 const float* __restrict__ wc, const float* __restrict__ bc,
                 const float* __restrict__ gammap, const int* __restrict__ Ntp,
                 float* __restrict__ out)
{
    __shared__ float ubuf[2][NXc + 2];   // ghost cells at [0] and [NXc+1], always 0
    __shared__ float s2red[NXc];
    __shared__ float vmred[NXc];
    __shared__ int   hist[NXc];

    const int t    = threadIdx.x;
    const int p    = t >> 1;     // grid point 0..63
    const int half = t & 1;      // 0 -> (w1,b1), 1 -> (w2,b2)
    const float bmask = (p == 0 || p == NXc - 1) ? 0.0f : 1.0f;  // Dirichlet mask

    const float gamma = gammap[0];
    const int   Nt    = Ntp[0];
    const float bcv   = bc[0];

    // Constants rounded exactly as the float64->float32 path in the reference.
    const float DTf  = (float)1e-4;
    const float R2DX = (float)(1.0 / (2.0 * (1.0 / 63.0)));          // 31.5 (exact)
    const float RDX2 = (float)(1.0 / ((1.0 / 63.0) * (1.0 / 63.0))); // 3969 (exact)
    const float TWO_L2E = (float)(2.0 * 1.4426950408889634074);

    // Per-thread weights in registers (pre-scaled by 2*log2e for the ex2 path).
    // Combine fold: sum_j cwr_j*(1-2*r_j) = (sum_j cwr_j) + sum_j (-2*cwr_j)*r_j
    const float* W  = half ? w2 : w1;
    const float* Bp = half ? b2 : b1;
    float wa[HIDc], wb[HIDc], wq[HIDc], bb[HIDc], cw2[HIDc];
    float csum = 0.0f;
#pragma unroll
    for (int j = 0; j < HIDc; j++) {
        wa[j]  = TWO_L2E * W[j * 3 + 0];
        wb[j]  = TWO_L2E * W[j * 3 + 1];
        wq[j]  = TWO_L2E * W[j * 3 + 2];
        bb[j]  = TWO_L2E * Bp[j];
        float c = wc[half * HIDc + j];
        cw2[j]  = -2.0f * c;
        csum   += c;
    }

    // Init shared buffers (ghosts zero in both buffers; never rewritten).
    if (t < NXc + 2) { ubuf[0][t] = 0.0f; ubuf[1][t] = 0.0f; }
    __syncthreads();
    if (t < NXc) ubuf[0][t + 1] = u0[t];
    __syncthreads();

    float* bufA = &ubuf[0][0];
    float* bufB = &ubuf[1][0];

    for (int it = 0; it < Nt; ++it) {
        const float um = bufA[p];
        const float uc = bufA[p + 1];
        const float up = bufA[p + 2];
        const float gx  = (up - um) * R2DX;
        const float lap = (up - 2.0f * uc + um) * RDX2;

        // Two accumulators: break the 16-deep dependent FMA chain.
        float s0 = csum, s1 = 0.0f;
#pragma unroll
        for (int j = 0; j < HIDc; j += 2) {
            float za = fmaf(lap, wq[j],   fmaf(gx, wb[j],   fmaf(uc, wa[j],   bb[j])));
            float zb = fmaf(lap, wq[j+1], fmaf(gx, wb[j+1], fmaf(uc, wa[j+1], bb[j+1])));
            float ra = rcpf(ex2f(za) + 1.0f);     // 1/(exp(2z)+1)
            float rb = rcpf(ex2f(zb) + 1.0f);
            s0 = fmaf(cw2[j],   ra, s0);          // += cwr*(1-2r), folded
            s1 = fmaf(cw2[j+1], rb, s1);
        }
        float s = s0 + s1;
        const float so = __shfl_xor_sync(0xffffffffu, s, 1);

        if (half == 0) {
            float tree = s + so + bcv;
            float core = fmaf(0.8f, lap, 0.5f * uc) - uc * uc * uc;
            float un   = fmaf(DTf, fmaf(gamma, tree, core), uc);
            bufB[p + 1] = un * bmask;             // branch-free Dirichlet BCs
        }
        __syncthreads();
        float* tmp = bufA; bufA = bufB; bufB = tmp;
    }

    // ---- Final statistics ----
    const float* uf = bufA + 1;
    if (t < NXc) {
        float v = uf[t];
        out[t]     = v;
        s2red[t]   = v * v;
        vmred[t]   = fabsf(v);
        hist[t]    = 0;
    }
    __syncthreads();

    if (t == 0) {
        float s2 = 0.0f, vmax = 0.0f;
        for (int i = 0; i < NXc; i++) {
            s2   += s2red[i];
            vmax  = fmaxf(vmax, vmred[i]);
        }
        out[NXc] = s2 * (1.0f / 64.0f);   // phi2 = mean(u^2); /64 exact

        const float vden = fmaxf(vmax, 1e-12f);
        for (int i = 0; i < NXc; i++) {
            float vn = vmred[i] / vden;   // in [0, 1]
            int b = (int)floorf(vn * 64.0f);
            if (b > 63) b = 63;
            if (b < 0)  b = 0;
            // Exact searchsorted(edges, vn, 'right') semantics: edges k/64 are
            // exact in fp32, so correct any rounding from the vn*64 multiply.
            while (b > 0  && vn <  (float)b       * (1.0f / 64.0f)) b--;
            while (b < 63 && vn >= (float)(b + 1) * (1.0f / 64.0f)) b++;
            hist[b]++;
        }
        float H = 0.0f;
        for (int i = 0; i < NXc; i++) {
            float pb = (float)hist[i] * (1.0f / 64.0f);  // sum==64, /64 exact
            H -= pb * logf(pb + 1e-12f);                 // empty bins contribute ~0
        }
        if (vmax < 1e-12f) H = 0.0f;
        out[NXc + 1] = H;
    }
}

extern "C" void kernel_launch(void* const* d_in, const int* in_sizes, int n_in,
                              void* d_out, int out_size) {
    const float* u0    = (const float*)d_in[0];
    const float* w1    = (const float*)d_in[1];
    const float* b1    = (const float*)d_in[2];
    const float* w2    = (const float*)d_in[3];
    const float* b2    = (const float*)d_in[4];
    const float* wc    = (const float*)d_in[5];
    const float* bc    = (const float*)d_in[6];
    const float* gamma = (const float*)d_in[7];
    const int*   Nt    = (const int*)d_in[8];
    float* out = (float*)d_out;

    scct_kernel<<<1, 128>>>(u0, w1, b1, w2, b2, wc, bc, gamma, Nt, out);
}

// round 4
// speedup vs baseline: 1.4675x; 1.4675x over previous
#include <cuda_runtime.h>

// SCCT_NGT: 5000-step explicit PDE loop on NX=64 with tiny MLP closure,
// then phi2 = mean(u^2) and histogram entropy H of |u|/max.
//
// One persistent CTA (128 threads = 4 warps, 1 per SMSP), u double-buffered in
// shared memory, one __syncthreads per step. Thread t handles point p = t>>1;
// half = t&1 selects (w1,b1,wc[:16]) vs (w2,b2,wc[16:]); the two halves'
// partial combine sums merge via __shfl_xor(s,1) — no extra barrier.
//
// R4 change: activation via MUFU.TANH (tanh.approx.f32) — 1 MUFU/unit instead
// of the 2-MUFU ex2+rcp path. MUFU floor halves: 16 warp-MUFU/step @ rt 8 =
// 128 cyc/step. Error budget: tanh.approx abs err ~5e-4 -> contractive
// dynamics give steady-state u drift ~1e-5, vs measured baseline rel_err
// 2.4e-7 and threshold 1e-3.

#define NXc 64
#define HIDc 16

__device__ __forceinline__ float tanhf_mufu(float x) {
    float y; asm("tanh.approx.f32 %0, %1;" : "=f"(y) : "f"(x)); return y;
}

__global__ __launch_bounds__(128, 1)
void scct_kernel(const float* __restrict__ u0,
                 const float* __restrict__ w1, const float* __restrict__ b1,
                 const float* __restrict__ w2, const float* __restrict__ b2,
                 const float* __restrict__ wc, const float* __restrict__ bc,
                 const float* __restrict__ gammap, const int* __restrict__ Ntp,
                 float* __restrict__ out)
{
    __shared__ float ubuf[2][NXc + 2];   // ghost cells at [0] and [NXc+1], always 0
    __shared__ float s2red[NXc];
    __shared__ float vmred[NXc];
    __shared__ int   hist[NXc];

    const int t    = threadIdx.x;
    const int p    = t >> 1;     // grid point 0..63
    const int half = t & 1;      // 0 -> (w1,b1), 1 -> (w2,b2)
    const float bmask = (p == 0 || p == NXc - 1) ? 0.0f : 1.0f;  // Dirichlet mask

    const float gamma = gammap[0];
    const int   Nt    = Ntp[0];
    const float bcv   = bc[0];

    // Constants rounded exactly as the float64->float32 path in the reference.
    const float DTf  = (float)1e-4;
    const float R2DX = (float)(1.0 / (2.0 * (1.0 / 63.0)));          // 31.5 (exact)
    const float RDX2 = (float)(1.0 / ((1.0 / 63.0) * (1.0 / 63.0))); // 3969 (exact)

    // Per-thread weights in registers (raw; tanh.approx takes z directly).
    const float* W  = half ? w2 : w1;
    const float* Bp = half ? b2 : b1;
    float wa[HIDc], wb[HIDc], wq[HIDc], bb[HIDc], cwr[HIDc];
#pragma unroll
    for (int j = 0; j < HIDc; j++) {
        wa[j]  = W[j * 3 + 0];
        wb[j]  = W[j * 3 + 1];
        wq[j]  = W[j * 3 + 2];
        bb[j]  = Bp[j];
        cwr[j] = wc[half * HIDc + j];
    }

    // Init shared buffers (ghosts zero in both buffers; never rewritten).
    if (t < NXc + 2) { ubuf[0][t] = 0.0f; ubuf[1][t] = 0.0f; }
    __syncthreads();
    if (t < NXc) ubuf[0][t + 1] = u0[t];
    __syncthreads();

    float* bufA = &ubuf[0][0];
    float* bufB = &ubuf[1][0];

    for (int it = 0; it < Nt; ++it) {
        const float um = bufA[p];
        const float uc = bufA[p + 1];
        const float up = bufA[p + 2];
        const float gx  = (up - um) * R2DX;
        const float lap = (up - 2.0f * uc + um) * RDX2;

        // Two accumulators: break the dependent FMA chain.
        float s0 = 0.0f, s1 = 0.0f;
#pragma unroll
        for (int j = 0; j < HIDc; j += 2) {
            float za = fmaf(lap, wq[j],   fmaf(gx, wb[j],   fmaf(uc, wa[j],   bb[j])));
            float zb = fmaf(lap, wq[j+1], fmaf(gx, wb[j+1], fmaf(uc, wa[j+1], bb[j+1])));
            float ta = tanhf_mufu(za);
            float tb = tanhf_mufu(zb);
            s0 = fmaf(cwr[j],   ta, s0);
            s1 = fmaf(cwr[j+1], tb, s1);
        }
        float s = s0 + s1;
        const float so = __shfl_xor_sync(0xffffffffu, s, 1);

        if (half == 0) {
            float tree = s + so + bcv;
            float core = fmaf(0.8f, lap, 0.5f * uc) - uc * uc * uc;
            float un   = fmaf(DTf, fmaf(gamma, tree, core), uc);
            bufB[p + 1] = un * bmask;             // branch-free Dirichlet BCs
        }
        __syncthreads();
        float* tmp = bufA; bufA = bufB; bufB = tmp;
    }

    // ---- Final statistics ----
    const float* uf = bufA + 1;
    if (t < NXc) {
        float v = uf[t];
        out[t]     = v;
        s2red[t]   = v * v;
        vmred[t]   = fabsf(v);
        hist[t]    = 0;
    }
    __syncthreads();

    if (t == 0) {
        float s2 = 0.0f, vmax = 0.0f;
        for (int i = 0; i < NXc; i++) {
            s2   += s2red[i];
            vmax  = fmaxf(vmax, vmred[i]);
        }
        out[NXc] = s2 * (1.0f / 64.0f);   // phi2 = mean(u^2); /64 exact

        const float vden = fmaxf(vmax, 1e-12f);
        for (int i = 0; i < NXc; i++) {
            float vn = vmred[i] / vden;   // in [0, 1]
            int b = (int)floorf(vn * 64.0f);
            if (b > 63) b = 63;
            if (b < 0)  b = 0;
            // Exact searchsorted(edges, vn, 'right') semantics: edges k/64 are
            // exact in fp32, so correct any rounding from the vn*64 multiply.
            while (b > 0  && vn <  (float)b       * (1.0f / 64.0f)) b--;
            while (b < 63 && vn >= (float)(b + 1) * (1.0f / 64.0f)) b++;
            hist[b]++;
        }
        float H = 0.0f;
        for (int i = 0; i < NXc; i++) {
            float pb = (float)hist[i] * (1.0f / 64.0f);  // sum==64, /64 exact
            H -= pb * logf(pb + 1e-12f);                 // empty bins contribute ~0
        }
        if (vmax < 1e-12f) H = 0.0f;
        out[NXc + 1] = H;
    }
}

extern "C" void kernel_launch(void* const* d_in, const int* in_sizes, int n_in,
                              void* d_out, int out_size) {
    const float* u0    = (const float*)d_in[0];
    const float* w1    = (const float*)d_in[1];
    const float* b1    = (const float*)d_in[2];
    const float* w2    = (const float*)d_in[3];
    const float* b2    = (const float*)d_in[4];
    const float* wc    = (const float*)d_in[5];
    const float* bc    = (const float*)d_in[6];
    const float* gamma = (const float*)d_in[7];
    const int*   Nt    = (const int*)d_in[8];
    float* out = (float*)d_out;

    scct_kernel<<<1, 128>>>(u0, w1, b1, w2, b2, wc, bc, gamma, Nt, out);
}

// round 7
// speedup vs baseline: 1.6747x; 1.1412x over previous
#include <cuda_runtime.h>

// SCCT_NGT: 5000-step explicit PDE loop on NX=64 with tiny MLP closure,
// then phi2 = mean(u^2) and histogram entropy H of |u|/max.
//
// One persistent CTA, 256 threads = 8 warps (2 per SMSP), u double-buffered
// in shared memory, one __syncthreads per step.
// Thread t: point p = t>>2, sub = t&3 selects an 8-unit slice of the 32
// hidden units (sub>>1 picks W1/W2, (sub&1)*8 the offset inside that half).
// The 4 per-point partial sums live in one lane quad -> combined with two
// __shfl_xor hops (1, 2); lane with sub==0 writes the updated point.
//
// Per-SMSP MUFU floor (layout-invariant): 64 warp-TANH/step over 4 SMSPs
// = 16 ops @ rt 8 = 128 cyc/step. 2 warps/SMSP hide leadin/shfl/tail
// latency under each other's MUFU issues.
// Stencil folded into weights: z = A*um + B*uc + C*up + bb.

#define NXc 64
#define HIDc 16
#define UPT 8   // hidden units per thread

__device__ __forceinline__ float tanhf_mufu(float x) {
    float y; asm("tanh.approx.f32 %0, %1;" : "=f"(y) : "f"(x)); return y;
}

__global__ __launch_bounds__(256, 1)
void scct_kernel(const float* __restrict__ u0,
                 const float* __restrict__ w1, const float* __restrict__ b1,
                 const float* __restrict__ w2, const float* __restrict__ b2,
                 const float* __restrict__ wc, const float* __restrict__ bc,
                 const float* __restrict__ gammap, const int* __restrict__ Ntp,
                 float* __restrict__ out)
{
    __shared__ float ubuf[2][NXc + 2];   // ghost cells at [0] and [NXc+1], always 0
    __shared__ float s2red[NXc];
    __shared__ float vmred[NXc];
    __shared__ int   hist[NXc];

    const int t   = threadIdx.x;
    const int p   = t >> 2;      // grid point 0..63
    const int sub = t & 3;       // 4 threads per point
    const float bmask = (p == 0 || p == NXc - 1) ? 0.0f : 1.0f;  // Dirichlet

    const float gamma = gammap[0];
    const int   Nt    = Ntp[0];
    const float bcv   = bc[0];

    const float DTf  = (float)1e-4;
    const float R2DX = 31.5f;     // 1/(2*DX), exact
    const float RDX2 = 3969.0f;   // 1/DX^2, exact

    // Masked per-thread update constants (zero on boundary threads -> un = 0).
    const float DTf_m  = DTf * bmask;
    const float DTg_m  = DTf * gamma * bmask;
    const float DTgb_m = DTf * gamma * bcv * bmask;
    const float K08R   = 0.8f * RDX2;        // core: (um+up) coeff of 0.8*lap
    const float C1     = 0.5f - 2.0f * K08R; // core: uc coeff

    // This thread's 8-unit weight slice, stencil pre-folded:
    //   z_j = um*(RDX2*wq - R2DX*wb) + uc*(wa - 2*RDX2*wq)
    //       + up*(R2DX*wb + RDX2*wq) + bb
    const float* W  = (sub >> 1) ? w2 : w1;
    const float* Bp = (sub >> 1) ? b2 : b1;
    const int j0 = (sub & 1) * UPT;          // 0 or 8 within the 16-unit half
    float Aw[UPT], Bw[UPT], Cw[UPT], bb[UPT], cwr[UPT];
#pragma unroll
    for (int k = 0; k < UPT; k++) {
        int j = j0 + k;
        float wa = W[j * 3 + 0];
        float wb = W[j * 3 + 1];
        float wq = W[j * 3 + 2];
        Aw[k]  = RDX2 * wq - R2DX * wb;
        Bw[k]  = wa - 2.0f * RDX2 * wq;
        Cw[k]  = R2DX * wb + RDX2 * wq;
        bb[k]  = Bp[j];
        cwr[k] = wc[(sub >> 1) * HIDc + j];
    }

    // Init shared buffers (ghosts zero in both buffers; never rewritten).
    if (t < NXc + 2) { ubuf[0][t] = 0.0f; ubuf[1][t] = 0.0f; }
    __syncthreads();
    if (t < NXc) ubuf[0][t + 1] = u0[t];
    __syncthreads();

    float* bufA = &ubuf[0][0];
    float* bufB = &ubuf[1][0];

    for (int it = 0; it < Nt; ++it) {
        const float um = bufA[p];
        const float uc = bufA[p + 1];
        const float up = bufA[p + 2];

        // core = 0.8*lap + 0.5*uc - uc^3 (folded); parallel to the tanh block
        const float core = fmaf(um + up, K08R, fmaf(uc, C1, -(uc * uc * uc)));
        const float base = fmaf(DTf_m, core, uc * bmask) + DTgb_m;

        float s0 = 0.0f, s1 = 0.0f;
#pragma unroll
        for (int k = 0; k < UPT; k += 2) {
            float za = fmaf(up, Cw[k],   fmaf(uc, Bw[k],   fmaf(um, Aw[k],   bb[k])));
            float zb = fmaf(up, Cw[k+1], fmaf(uc, Bw[k+1], fmaf(um, Aw[k+1], bb[k+1])));
            float ta = tanhf_mufu(za);
            float tb = tanhf_mufu(zb);
            s0 = fmaf(cwr[k],   ta, s0);
            s1 = fmaf(cwr[k+1], tb, s1);
        }
        float s = s0 + s1;
        // Quad reduce: lanes {4q..4q+3} hold the 4 slices of point p.
        s += __shfl_xor_sync(0xffffffffu, s, 1);
        s += __shfl_xor_sync(0xffffffffu, s, 2);

        if (sub == 0) {
            bufB[p + 1] = fmaf(DTg_m, s, base);
        }
        __syncthreads();
        float* tmp = bufA; bufA = bufB; bufB = tmp;
    }

    // ---- Final statistics ----
    const float* uf = bufA + 1;
    if (t < NXc) {
        float v = uf[t];
        out[t]     = v;
        s2red[t]   = v * v;
        vmred[t]   = fabsf(v);
        hist[t]    = 0;
    }
    __syncthreads();

    if (t == 0) {
        float s2 = 0.0f, vmax = 0.0f;
        for (int i = 0; i < NXc; i++) {
            s2   += s2red[i];
            vmax  = fmaxf(vmax, vmred[i]);
        }
        out[NXc] = s2 * (1.0f / 64.0f);   // phi2 = mean(u^2)

        const float vden = fmaxf(vmax, 1e-12f);
        for (int i = 0; i < NXc; i++) {
            float vn = vmred[i] / vden;   // in [0, 1]
            int b = (int)floorf(vn * 64.0f);
            if (b > 63) b = 63;
            if (b < 0)  b = 0;
            // Exact searchsorted(edges, vn, 'right'): edges k/64 exact in fp32.
            while (b > 0  && vn <  (float)b       * (1.0f / 64.0f)) b--;
            while (b < 63 && vn >= (float)(b + 1) * (1.0f / 64.0f)) b++;
            hist[b]++;
        }
        float H = 0.0f;
        for (int i = 0; i < NXc; i++) {
            float pb = (float)hist[i] * (1.0f / 64.0f);
            H -= pb * logf(pb + 1e-12f);
        }
        if (vmax < 1e-12f) H = 0.0f;
        out[NXc + 1] = H;
    }
}

extern "C" void kernel_launch(void* const* d_in, const int* in_sizes, int n_in,
                              void* d_out, int out_size) {
    const float* u0    = (const float*)d_in[0];
    const float* w1    = (const float*)d_in[1];
    const float* b1    = (const float*)d_in[2];
    const float* w2    = (const float*)d_in[3];
    const float* b2    = (const float*)d_in[4];
    const float* wc    = (const float*)d_in[5];
    const float* bc    = (const float*)d_in[6];
    const float* gamma = (const float*)d_in[7];
    const int*   Nt    = (const int*)d_in[8];
    float* out = (float*)d_out;

    scct_kernel<<<1, 256>>>(u0, w1, b1, w2, b2, wc, bc, gamma, Nt, out);
}